// round 16
// baseline (speedup 1.0000x reference)
#include <cuda_runtime.h>
#include <math.h>

// ---- problem config ----
#define BB 4
#define NN 16384
#define REG_CH 76
#define POST 128
#define PSEL 256               // candidate budget (128th kept ~rank 130; 2x margin)
#define MWS (PSEL / 32)        // sup words per row = 8
#define CANDP 512              // primary candidate cap
#define CANDM 1024             // mid fallback
#define CANDF 4096             // max fallback
#define NMS_THRESH 0.8f
#define TWO_PI_F 6.2831853071795864769f
#define PI_F 3.14159265358979323846f
#define APC_F 0.52359877559829887308f       // 2pi/12
#define APC_HALF_F 0.26179938779914943654f  // pi/12

#define RSTRIDE 79             // 76 reg + 3 xyz; odd -> conflict-free LDS

// ---- dynamic smem layout (bytes); regions time-multiplexed ----
// phase 1: rankP [0,4096) | cand [81920,114688)
// phase 2: rowsbuf [0,80896) | score/bev/sar/box/sorted high
// phase 3: sup [0,8192)
#define OFF_RANK   0                        // 1024 i32 = 4096 (phase 1 only)
#define OFF_ROWS   0                        // 256*79*4 = 80896
#define OFF_SUP    0                        // 256*8*4 = 8192 (phase 3)
#define OFF_CAND   81920                    // 4096 u64 = 32768 -> 114688
#define OFF_SCORE  114688                   // 256 f32 = 1024
#define OFF_BEV4   115712                   // 256 float4 = 4096
#define OFF_SAR    119808                   // 256 f32 = 1024
#define OFF_BOX    120832                   // 256*7 f32 = 7168 -> 128000
#define OFF_SORT   128000                   // 256 u64 = 2048 -> 130048
#define SMEM_BYTES 130048

__device__ __forceinline__ unsigned desc_key(float f) {
    unsigned u = __float_as_uint(f);
    unsigned asc = (u & 0x80000000u) ? ~u : (u | 0x80000000u);
    return ~asc;   // ascending key order == descending score order
}
__device__ __forceinline__ float key_to_score(unsigned desc) {
    unsigned asc = ~desc;
    unsigned u = (asc & 0x80000000u) ? (asc ^ 0x80000000u) : ~asc;
    return __uint_as_float(u);
}

// hybrid bitonic sort (deep fallback only), n power of 2, 1024 threads.
__device__ __forceinline__ void bitonic_hybrid(unsigned long long* a, int n, int tid) {
    const int lane = tid & 31;
    const int wid = tid >> 5;
    for (int k = 2; k <= n; k <<= 1) {
        for (int j = k >> 1; j >= 32; j >>= 1) {
            for (int i = tid; i < n; i += 1024) {
                int ixj = i ^ j;
                if (ixj > i) {
                    unsigned long long x = a[i], y = a[ixj];
                    bool asc = ((i & k) == 0);
                    if ((x > y) == asc) { a[i] = y; a[ixj] = x; }
                }
            }
            __syncthreads();
        }
        int jtop = (k >> 1) < 16 ? (k >> 1) : 16;
        for (int g = wid; g < (n >> 5); g += 32) {
            int i = (g << 5) + lane;
            unsigned long long v = a[i];
            bool asc = ((i & k) == 0);
            for (int j = jtop; j >= 1; j >>= 1) {
                unsigned long long p = __shfl_xor_sync(0xffffffffu, v, j);
                bool takemin = (((lane & j) == 0) == asc);
                v = takemin ? (v < p ? v : p) : (v > p ? v : p);
            }
            a[i] = v;
        }
        __syncthreads();
    }
}

// ============================================================
// One block per image.
// ============================================================
__global__ void __launch_bounds__(1024, 1)
fused_kernel(const float* __restrict__ scores,
             const float* __restrict__ reg,
             const float* __restrict__ xyz,
             const float* __restrict__ anchor,
             float* __restrict__ out) {
    extern __shared__ char sm[];
    unsigned long long* cand = (unsigned long long*)(sm + OFF_CAND);
    unsigned long long* sorted = (unsigned long long*)(sm + OFF_SORT);
    int* rankP = (int*)(sm + OFF_RANK);
    float* rowsbuf = (float*)(sm + OFF_ROWS);
    unsigned* sup = (unsigned*)(sm + OFF_SUP);
    float4* sbev = (float4*)(sm + OFF_BEV4);     // (x1,z1,x2,z2)
    float* sar = (float*)(sm + OFF_SAR);
    float* boxS = (float*)(sm + OFF_BOX);
    float* scoreS = (float*)(sm + OFF_SCORE);

    __shared__ unsigned wsum[32];
    __shared__ unsigned bcast;
    __shared__ unsigned zrow[MWS];
    __shared__ int sCnt, sKeepCnt;
    __shared__ int keep[POST];

    const int img = blockIdx.x;
    const int tid = threadIdx.x;
    const int lane = tid & 31;
    const int wid = tid >> 5;
    const float4* sc4 = (const float4*)(scores + (size_t)img * NN);

    // ========== Stage A: register keys + ZERO-round static threshold ==========
    unsigned uk[16];
    #pragma unroll
    for (int c = 0; c < 4; c++) {
        float4 v = sc4[c * 1024 + tid];
        uk[c * 4 + 0] = desc_key(v.x);
        uk[c * 4 + 1] = desc_key(v.y);
        uk[c * 4 + 2] = desc_key(v.z);
        uk[c * 4 + 3] = desc_key(v.w);
    }
    if (tid == 0) sCnt = 0;
    if (tid < MWS) zrow[tid] = 0;
    __syncthreads();

    #define COMPACT(TT)                                                        \
    {                                                                          \
        unsigned s = 0;                                                        \
        _Pragma("unroll")                                                      \
        for (int e = 0; e < 16; e++) s += (uk[e] <= (TT));                     \
        unsigned pfx = s;                                                      \
        _Pragma("unroll")                                                      \
        for (int d = 1; d < 32; d <<= 1) {                                     \
            unsigned y = __shfl_up_sync(0xffffffffu, pfx, d);                  \
            if (lane >= d) pfx += y;                                           \
        }                                                                      \
        unsigned wtot = __shfl_sync(0xffffffffu, pfx, 31);                     \
        unsigned excl = pfx - s;                                               \
        unsigned base = 0;                                                     \
        if (lane == 0 && wtot > 0) base = atomicAdd(&sCnt, (int)wtot);         \
        base = __shfl_sync(0xffffffffu, base, 0);                              \
        int pos = (int)(base + excl);                                          \
        _Pragma("unroll")                                                      \
        for (int e = 0; e < 16; e++) {                                         \
            if (uk[e] <= (TT)) {                                               \
                int idx = (((e >> 2) * 1024 + tid) << 2) + (e & 3);            \
                if (pos < CANDF)                                               \
                    cand[pos] = ((unsigned long long)uk[e] << 32) | (unsigned)idx; \
                pos++;                                                         \
            }                                                                  \
        }                                                                      \
    }

    const unsigned KT = desc_key(2.0f);   // N(0,1): E[count>2sigma] ~ 373
    COMPACT(KT);
    __syncthreads();
    int C = sCnt;

    if (C >= PSEL && C <= CANDP) {
        // ===== primary: pad + SPLIT rank-select (all 1024 threads) =====
        for (int p = C + tid; p < CANDP; p += 1024)
            cand[p] = 0xffffffffffffffffull;
        __syncthreads();
        {
            const int i = tid & (CANDP - 1);
            const int h = tid >> 9;                 // half 0/1
            unsigned long long my = cand[i];
            int half0 = C >> 1;
            int jb = h ? half0 : 0;
            int je = h ? C : half0;
            int rk = 0;
            #pragma unroll 8
            for (int j = jb; j < je; j++) rk += (cand[j] < my);
            rankP[tid] = rk;
        }
        __syncthreads();
        if (tid < CANDP) {
            int rank = rankP[tid] + rankP[tid + CANDP];
            if (rank < PSEL) sorted[rank] = cand[tid];
        }
        __syncthreads();
    } else {
        // ===== fallback: seeded ternary bisection (data defied statistics) =====
        if (tid == 0) sCnt = 0;
        __syncthreads();
        #define DUAL_COUNT(TA, TB, OUTVAR)                                     \
        {                                                                      \
            unsigned _c = 0;                                                   \
            _Pragma("unroll")                                                  \
            for (int _e = 0; _e < 16; _e++)                                    \
                _c += (uk[_e] <= (TA)) + ((unsigned)(uk[_e] <= (TB)) << 16);   \
            unsigned _wc = __reduce_add_sync(0xffffffffu, _c);                 \
            if (lane == 0) wsum[wid] = _wc;                                    \
            __syncthreads();                                                   \
            if (wid == 0) {                                                    \
                unsigned _t = __reduce_add_sync(0xffffffffu, wsum[lane]);      \
                if (lane == 0) bcast = _t;                                     \
            }                                                                  \
            __syncthreads();                                                   \
            OUTVAR = bcast;                                                    \
        }
        unsigned lo, hi, chi;
        {
            const unsigned s1 = desc_key(2.45f);
            const unsigned s2 = desc_key(1.70f);
            unsigned cc;
            DUAL_COUNT(s1, s2, cc);
            unsigned a1 = cc & 0xffffu, a2 = cc >> 16;
            if (a1 >= PSEL)      { lo = 0u; hi = s1; chi = a1; }
            else if (a2 >= PSEL) { lo = s1; hi = s2; chi = a2; }
            else                 { lo = s2; hi = 0xffffffffu; chi = NN; }
        }
        while (!(chi >= PSEL && chi <= CANDP) && (hi - lo) >= 3u) {
            unsigned span = hi - lo;
            unsigned m1 = lo + span / 3u;
            unsigned m2 = lo + (span / 3u) * 2u;
            unsigned cc;
            DUAL_COUNT(m1, m2, cc);
            unsigned a1 = cc & 0xffffu, a2 = cc >> 16;
            if (a1 >= PSEL)      { hi = m1; chi = a1; }
            else if (a2 >= PSEL) { lo = m1; hi = m2; chi = a2; }
            else                 { lo = m2; }
        }
        const unsigned T = hi;
        C = (int)chi;
        COMPACT(T);
        __syncthreads();
        if (C <= CANDP) {
            for (int p = C + tid; p < CANDP; p += 1024)
                cand[p] = 0xffffffffffffffffull;
            __syncthreads();
            if (tid < CANDP) {
                unsigned long long my = cand[tid];
                int rank = 0;
                #pragma unroll 8
                for (int j = 0; j < CANDP; j++) rank += (cand[j] < my);
                if (rank < PSEL) sorted[rank] = my;
            }
            __syncthreads();
        } else {
            const int NS = (C <= CANDM) ? CANDM : CANDF;
            for (int p = C + tid; p < NS; p += 1024)
                cand[p] = 0xffffffffffffffffull;
            __syncthreads();
            bitonic_hybrid(cand, NS, tid);
            if (tid < PSEL) sorted[tid] = cand[tid];
            __syncthreads();
        }
    }

    // ========== Stage B1: coalesced copy (fully unrolled -> batched LDGs) ==========
    {
        #pragma unroll
        for (int k = 0; k < PSEL / 32; k++) {
            int rr = wid + k * 32;
            unsigned long long key = sorted[rr];     // uniform -> broadcast LDS
            int idx = (int)(key & 0xffffffffu);
            const float* r = reg + (size_t)(img * NN + idx) * REG_CH;
            float* dst = rowsbuf + rr * RSTRIDE;
            float a = r[lane];
            float b = r[32 + lane];
            float c = 0.0f;
            if (lane < 12)      c = r[64 + lane];
            else if (lane < 15) c = xyz[(size_t)(img * NN + idx) * 3 + (lane - 12)];
            dst[lane]      = a;
            dst[32 + lane] = b;
            if (lane < 15) dst[64 + lane] = c;
            if (lane == 15) scoreS[rr] = key_to_score((unsigned)(key >> 32));
        }
    }
    __syncthreads();

    // ========== Stage B2: decode from smem (thread-per-row, conflict-free) ==========
    const float ah = anchor[0], aw = anchor[1], al = anchor[2];
    if (tid < PSEL) {
        const float* r = rowsbuf + tid * RSTRIDE;

        int xb = 0; float bv = r[0];
        #pragma unroll
        for (int t = 1; t < 12; t++) if (r[t] > bv) { bv = r[t]; xb = t; }
        int zb = 0; bv = r[12];
        #pragma unroll
        for (int t = 1; t < 12; t++) if (r[12 + t] > bv) { bv = r[12 + t]; zb = t; }

        float pos_x = __fadd_rn(__fsub_rn(__fadd_rn(__fmul_rn((float)xb, 0.5f), 0.25f), 3.0f),
                                __fmul_rn(r[24 + xb], 0.5f));
        float pos_z = __fadd_rn(__fsub_rn(__fadd_rn(__fmul_rn((float)zb, 0.5f), 0.25f), 3.0f),
                                __fmul_rn(r[36 + zb], 0.5f));
        float x = __fadd_rn(pos_x, r[76]);
        float z = __fadd_rn(pos_z, r[78]);
        float y = __fadd_rn(r[77], r[48]);

        int rb = 0; bv = r[49];
        #pragma unroll
        for (int t = 1; t < 12; t++) if (r[49 + t] > bv) { bv = r[49 + t]; rb = t; }
        float ry = __fadd_rn(__fmul_rn((float)rb, APC_F),
                             __fmul_rn(r[61 + rb], APC_HALF_F));
        float rem = fmodf(ry, TWO_PI_F);
        if (rem != 0.0f && rem < 0.0f) rem = __fadd_rn(rem, TWO_PI_F);
        ry = rem;
        if (ry > PI_F) ry = __fsub_rn(ry, TWO_PI_F);

        float h = __fadd_rn(__fmul_rn(r[73], ah), ah);
        float w = __fadd_rn(__fmul_rn(r[74], aw), aw);
        float l = __fadd_rn(__fmul_rn(r[75], al), al);
        y = __fadd_rn(y, __fmul_rn(h, 0.5f));

        float* bo = boxS + tid * 7;
        bo[0] = x; bo[1] = y; bo[2] = z; bo[3] = h; bo[4] = w; bo[5] = l; bo[6] = ry;

        float x1 = __fsub_rn(x, __fmul_rn(l, 0.5f));
        float x2 = __fadd_rn(x, __fmul_rn(l, 0.5f));
        float z1 = __fsub_rn(z, __fmul_rn(w, 0.5f));
        float z2 = __fadd_rn(z, __fmul_rn(w, 0.5f));
        sbev[tid] = make_float4(x1, z1, x2, z2);
        sar[tid] = __fmul_rn(__fsub_rn(x2, x1), __fsub_rn(z2, z1));
    }
    __syncthreads();   // rowsbuf dead; sup may now overwrite [0,8192)

    // ========== Stage C: balanced pairwise suppression bitmask + zrow ==========
    {
        const int pr = tid & 127;                // pair id
        const int w = tid >> 7;                  // word 0..7
        #pragma unroll
        for (int half = 0; half < 2; half++) {
            const int i = half ? (PSEL - 1 - pr) : pr;
            float4 bi = sbev[i];
            float ai = sar[i];
            unsigned bits = 0;
            int jbase = w << 5;
            if (jbase + 31 > i) {
                #pragma unroll 4
                for (int b = 0; b < 32; b++) {
                    int j = jbase + b;
                    if (j <= i) continue;
                    float4 bj = sbev[j];
                    float iw = fmaxf(__fsub_rn(fminf(bi.z, bj.z), fmaxf(bi.x, bj.x)), 0.0f);
                    float ih = fmaxf(__fsub_rn(fminf(bi.w, bj.w), fmaxf(bi.y, bj.y)), 0.0f);
                    float inter = __fmul_rn(iw, ih);
                    if (inter > 0.0f) {
                        float denom = __fsub_rn(__fadd_rn(ai, sar[j]), inter);
                        float iou = __fdiv_rn(inter, denom);
                        if (iou > NMS_THRESH) bits |= (1u << b);
                    }
                }
            }
            sup[i * MWS + w] = bits;
            if (bits) atomicOr(&zrow[i >> 5], 1u << (i & 31));
        }
    }
    __syncthreads();

    // ========== Stage D: bulk-skip greedy (warp 0) ==========
    if (wid == 0) {
        unsigned A = (lane < MWS) ? 0xffffffffu : 0u;
        unsigned Z = (lane < MWS) ? zrow[lane] : 0u;
        int cnt = 0;
        int w = 0;
        while (cnt < POST && w < MWS) {
            unsigned word = __shfl_sync(0xffffffffu, A, w);
            unsigned zw   = __shfl_sync(0xffffffffu, Z, w);
            unsigned danger = word & zw;
            if (danger == 0) {
                int nb = __popc(word);
                int take = min(nb, POST - cnt);
                if (lane < take) {
                    int bit = __fns(word, 0, lane + 1);
                    keep[cnt + lane] = (w << 5) + bit;
                }
                cnt += take;
                w++;
            } else {
                int bs = __ffs(danger) - 1;
                unsigned prefix = word & ((1u << bs) - 1u);
                int nb = __popc(prefix);
                int take = min(nb, POST - cnt);
                if (lane < take) {
                    int bit = __fns(prefix, 0, lane + 1);
                    keep[cnt + lane] = (w << 5) + bit;
                }
                cnt += take;
                if (cnt >= POST) break;
                int bi = (w << 5) + bs;
                if (lane == 0) keep[cnt] = bi;
                cnt++;
                unsigned srow = (lane < MWS) ? sup[bi * MWS + lane] : 0u;
                A &= ~srow;
                if (lane == w) {
                    unsigned clr = (bs == 31) ? 0xffffffffu : ((1u << (bs + 1)) - 1u);
                    A &= ~clr;
                }
            }
        }
        if (lane == 0) sKeepCnt = cnt;
    }
    __syncthreads();

    // ========== Stage E: gather output ==========
    const int cnt = sKeepCnt;
    float* ob = out + (size_t)img * POST * 7;
    float* os = out + (size_t)BB * POST * 7 + (size_t)img * POST;
    if (tid < POST) {
        int p = tid;
        if (p < cnt) {
            int ki = keep[p];
            const float* bo = boxS + ki * 7;
            #pragma unroll
            for (int c = 0; c < 7; c++) ob[p * 7 + c] = bo[c];
            os[p] = scoreS[ki];
        } else {
            #pragma unroll
            for (int c = 0; c < 7; c++) ob[p * 7 + c] = 0.0f;
            os[p] = 0.0f;
        }
    }
}

// ============================================================
extern "C" void kernel_launch(void* const* d_in, const int* in_sizes, int n_in,
                              void* d_out, int out_size) {
    const float* scores = (const float*)d_in[0];   // (B,N)
    const float* reg    = (const float*)d_in[1];   // (B,N,76)
    const float* xyz    = (const float*)d_in[2];   // (B,N,3)
    const float* anchor = (const float*)d_in[3];   // (3,)
    float* out = (float*)d_out;

    static bool attr_set = false;
    if (!attr_set) {
        cudaFuncSetAttribute(fused_kernel,
                             cudaFuncAttributeMaxDynamicSharedMemorySize,
                             SMEM_BYTES);
        attr_set = true;
    }

    fused_kernel<<<BB, 1024, SMEM_BYTES>>>(scores, reg, xyz, anchor, out);
}

// round 17
// speedup vs baseline: 1.2174x; 1.2174x over previous
#include <cuda_runtime.h>
#include <math.h>

// ---- problem config ----
#define BB 4
#define NN 16384
#define REG_CH 76
#define POST 128
#define PSEL 256               // candidate budget (128th kept ~rank 130; 2x margin)
#define MWS (PSEL / 32)        // sup words per row = 8
#define CANDP 512              // primary candidate cap
#define CANDM 1024             // mid fallback
#define CANDF 4096             // max fallback
#define NMS_THRESH 0.8f
#define TWO_PI_F 6.2831853071795864769f
#define PI_F 3.14159265358979323846f
#define APC_F 0.52359877559829887308f       // 2pi/12
#define APC_HALF_F 0.26179938779914943654f  // pi/12

#define RSTRIDE 79             // 76 reg + 3 xyz; odd -> conflict-free LDS

// ---- dynamic smem layout (bytes); regions time-multiplexed ----
#define OFF_ROWS   0                        // 256*79*4 = 80896
#define OFF_SUP    0                        // 256*8*4 = 8192 (phase 3)
#define OFF_CAND   81920                    // 4096 u64 = 32768 -> 114688  (grouped at +512)
#define OFF_SCORE  114688                   // 256 f32 = 1024
#define OFF_BEV4   115712                   // 256 float4 = 4096
#define OFF_SAR    119808                   // 256 f32 = 1024
#define OFF_BOX    120832                   // 256*7 f32 = 7168 -> 128000
#define OFF_SORT   128000                   // 256 u64 = 2048 -> 130048
#define SMEM_BYTES 130048

__device__ __forceinline__ unsigned desc_key(float f) {
    unsigned u = __float_as_uint(f);
    unsigned asc = (u & 0x80000000u) ? ~u : (u | 0x80000000u);
    return ~asc;   // ascending key order == descending score order
}
__device__ __forceinline__ float key_to_score(unsigned desc) {
    unsigned asc = ~desc;
    unsigned u = (asc & 0x80000000u) ? (asc ^ 0x80000000u) : ~asc;
    return __uint_as_float(u);
}

// hybrid bitonic sort (deep fallback only), n power of 2, 1024 threads.
__device__ __forceinline__ void bitonic_hybrid(unsigned long long* a, int n, int tid) {
    const int lane = tid & 31;
    const int wid = tid >> 5;
    for (int k = 2; k <= n; k <<= 1) {
        for (int j = k >> 1; j >= 32; j >>= 1) {
            for (int i = tid; i < n; i += 1024) {
                int ixj = i ^ j;
                if (ixj > i) {
                    unsigned long long x = a[i], y = a[ixj];
                    bool asc = ((i & k) == 0);
                    if ((x > y) == asc) { a[i] = y; a[ixj] = x; }
                }
            }
            __syncthreads();
        }
        int jtop = (k >> 1) < 16 ? (k >> 1) : 16;
        for (int g = wid; g < (n >> 5); g += 32) {
            int i = (g << 5) + lane;
            unsigned long long v = a[i];
            bool asc = ((i & k) == 0);
            for (int j = jtop; j >= 1; j >>= 1) {
                unsigned long long p = __shfl_xor_sync(0xffffffffu, v, j);
                bool takemin = (((lane & j) == 0) == asc);
                v = takemin ? (v < p ? v : p) : (v > p ? v : p);
            }
            a[i] = v;
        }
        __syncthreads();
    }
}

// ============================================================
// One block per image.
// ============================================================
__global__ void __launch_bounds__(1024, 1)
fused_kernel(const float* __restrict__ scores,
             const float* __restrict__ reg,
             const float* __restrict__ xyz,
             const float* __restrict__ anchor,
             float* __restrict__ out) {
    extern __shared__ char sm[];
    unsigned long long* cand = (unsigned long long*)(sm + OFF_CAND);
    unsigned long long* grouped = cand + CANDP;          // 512 u64, inside cand region
    unsigned long long* sorted = (unsigned long long*)(sm + OFF_SORT);
    float* rowsbuf = (float*)(sm + OFF_ROWS);
    unsigned* sup = (unsigned*)(sm + OFF_SUP);
    float4* sbev = (float4*)(sm + OFF_BEV4);     // (x1,z1,x2,z2)
    float* sar = (float*)(sm + OFF_SAR);
    float* boxS = (float*)(sm + OFF_BOX);
    float* scoreS = (float*)(sm + OFF_SCORE);

    __shared__ unsigned wsum[32];
    __shared__ unsigned bcast;
    __shared__ unsigned bhist[256];   // bucket counts
    __shared__ unsigned bpfx[256];    // inclusive ascending prefix
    __shared__ unsigned zrow[MWS];
    __shared__ int sCnt, sKeepCnt;
    __shared__ int keep[POST];

    const int img = blockIdx.x;
    const int tid = threadIdx.x;
    const int lane = tid & 31;
    const int wid = tid >> 5;
    const float4* sc4 = (const float4*)(scores + (size_t)img * NN);

    // ========== Stage A: register keys + ZERO-round static threshold ==========
    unsigned uk[16];
    #pragma unroll
    for (int c = 0; c < 4; c++) {
        float4 v = sc4[c * 1024 + tid];
        uk[c * 4 + 0] = desc_key(v.x);
        uk[c * 4 + 1] = desc_key(v.y);
        uk[c * 4 + 2] = desc_key(v.z);
        uk[c * 4 + 3] = desc_key(v.w);
    }
    if (tid == 0) sCnt = 0;
    if (tid < MWS) zrow[tid] = 0;
    if (tid < 256) bhist[tid] = 0;
    __syncthreads();

    #define COMPACT(TT)                                                        \
    {                                                                          \
        unsigned s = 0;                                                        \
        _Pragma("unroll")                                                      \
        for (int e = 0; e < 16; e++) s += (uk[e] <= (TT));                     \
        unsigned pfx = s;                                                      \
        _Pragma("unroll")                                                      \
        for (int d = 1; d < 32; d <<= 1) {                                     \
            unsigned y = __shfl_up_sync(0xffffffffu, pfx, d);                  \
            if (lane >= d) pfx += y;                                           \
        }                                                                      \
        unsigned wtot = __shfl_sync(0xffffffffu, pfx, 31);                     \
        unsigned excl = pfx - s;                                               \
        unsigned base = 0;                                                     \
        if (lane == 0 && wtot > 0) base = atomicAdd(&sCnt, (int)wtot);         \
        base = __shfl_sync(0xffffffffu, base, 0);                              \
        int pos = (int)(base + excl);                                          \
        _Pragma("unroll")                                                      \
        for (int e = 0; e < 16; e++) {                                         \
            if (uk[e] <= (TT)) {                                               \
                int idx = (((e >> 2) * 1024 + tid) << 2) + (e & 3);            \
                if (pos < CANDF)                                               \
                    cand[pos] = ((unsigned long long)uk[e] << 32) | (unsigned)idx; \
                pos++;                                                         \
            }                                                                  \
        }                                                                      \
    }

    const unsigned KT = desc_key(2.0f);   // N(0,1): E[count>2sigma] ~ 373
    COMPACT(KT);
    __syncthreads();
    int C = sCnt;

    if (C >= PSEL && C <= CANDP) {
        // ===== primary: bucketed rank (exact; ~14 compares/candidate) =====
        // bucket = min((KT - k32) >> 16, 255): order-consistent, reversed vs key
        unsigned myb = 0, mys = 0;
        unsigned long long mykey = 0;
        if (tid < C) {
            mykey = cand[tid];
            unsigned u = KT - (unsigned)(mykey >> 32);
            myb = u >> 16; if (myb > 255u) myb = 255u;
            mys = atomicAdd(&bhist[myb], 1u);
        }
        __syncthreads();
        // inclusive ascending prefix of bhist[256] (8 warps x 32)
        {
            unsigned v = 0, x = 0;
            if (tid < 256) {
                v = bhist[tid];
                x = v;
                #pragma unroll
                for (int d = 1; d < 32; d <<= 1) {
                    unsigned y = __shfl_up_sync(0xffffffffu, x, d);
                    if (lane >= d) x += y;
                }
                if (lane == 31) wsum[wid] = x;
            }
            __syncthreads();
            if (tid < 8) {
                unsigned w = wsum[tid];
                // serial-ish scan over 8 values via shuffle in warp 0
                unsigned ww = w;
                #pragma unroll
                for (int d = 1; d < 8; d <<= 1) {
                    unsigned y = __shfl_up_sync(0x000000ffu, ww, d);
                    if (tid >= d) ww += y;
                }
                wsum[tid] = ww;   // inclusive over warp sums
            }
            __syncthreads();
            if (tid < 256) {
                unsigned incl = x + ((wid > 0) ? wsum[wid - 1] : 0u);
                bpfx[tid] = incl;   // inclusive ascending prefix
            }
        }
        __syncthreads();
        // scatter to bucket-grouped order; base[b] = C - inclusive[b] (reversed)
        if (tid < C) {
            unsigned base = (unsigned)C - bpfx[myb];
            grouped[base + mys] = mykey;
        }
        __syncthreads();
        // exact rank within bucket
        if (tid < C) {
            unsigned long long gk = grouped[tid];
            unsigned u = KT - (unsigned)(gk >> 32);
            unsigned b = u >> 16; if (b > 255u) b = 255u;
            unsigned incl = bpfx[b];
            unsigned cnt = bhist[b];
            int st = C - (int)incl;          // bucket start in grouped[]
            int rk = st;
            for (int j = st; j < st + (int)cnt; j++)
                rk += (grouped[j] < gk);
            if (rk < PSEL) sorted[rk] = gk;
        }
        __syncthreads();
    } else {
        // ===== fallback: seeded ternary bisection (data defied statistics) =====
        if (tid == 0) sCnt = 0;
        __syncthreads();
        #define DUAL_COUNT(TA, TB, OUTVAR)                                     \
        {                                                                      \
            unsigned _c = 0;                                                   \
            _Pragma("unroll")                                                  \
            for (int _e = 0; _e < 16; _e++)                                    \
                _c += (uk[_e] <= (TA)) + ((unsigned)(uk[_e] <= (TB)) << 16);   \
            unsigned _wc = __reduce_add_sync(0xffffffffu, _c);                 \
            if (lane == 0) wsum[wid] = _wc;                                    \
            __syncthreads();                                                   \
            if (wid == 0) {                                                    \
                unsigned _t = __reduce_add_sync(0xffffffffu, wsum[lane]);      \
                if (lane == 0) bcast = _t;                                     \
            }                                                                  \
            __syncthreads();                                                   \
            OUTVAR = bcast;                                                    \
        }
        unsigned lo, hi, chi;
        {
            const unsigned s1 = desc_key(2.45f);
            const unsigned s2 = desc_key(1.70f);
            unsigned cc;
            DUAL_COUNT(s1, s2, cc);
            unsigned a1 = cc & 0xffffu, a2 = cc >> 16;
            if (a1 >= PSEL)      { lo = 0u; hi = s1; chi = a1; }
            else if (a2 >= PSEL) { lo = s1; hi = s2; chi = a2; }
            else                 { lo = s2; hi = 0xffffffffu; chi = NN; }
        }
        while (!(chi >= PSEL && chi <= CANDP) && (hi - lo) >= 3u) {
            unsigned span = hi - lo;
            unsigned m1 = lo + span / 3u;
            unsigned m2 = lo + (span / 3u) * 2u;
            unsigned cc;
            DUAL_COUNT(m1, m2, cc);
            unsigned a1 = cc & 0xffffu, a2 = cc >> 16;
            if (a1 >= PSEL)      { hi = m1; chi = a1; }
            else if (a2 >= PSEL) { lo = m1; hi = m2; chi = a2; }
            else                 { lo = m2; }
        }
        const unsigned T = hi;
        C = (int)chi;
        COMPACT(T);
        __syncthreads();
        if (C <= CANDP) {
            for (int p = C + tid; p < CANDP; p += 1024)
                cand[p] = 0xffffffffffffffffull;
            __syncthreads();
            if (tid < CANDP) {
                unsigned long long my = cand[tid];
                int rank = 0;
                #pragma unroll 8
                for (int j = 0; j < CANDP; j++) rank += (cand[j] < my);
                if (rank < PSEL) sorted[rank] = my;
            }
            __syncthreads();
        } else {
            const int NS = (C <= CANDM) ? CANDM : CANDF;
            for (int p = C + tid; p < NS; p += 1024)
                cand[p] = 0xffffffffffffffffull;
            __syncthreads();
            bitonic_hybrid(cand, NS, tid);
            if (tid < PSEL) sorted[tid] = cand[tid];
            __syncthreads();
        }
    }

    // ========== Stage B1: coalesced copy (fully unrolled -> batched LDGs) ==========
    {
        #pragma unroll
        for (int k = 0; k < PSEL / 32; k++) {
            int rr = wid + k * 32;
            unsigned long long key = sorted[rr];     // uniform -> broadcast LDS
            int idx = (int)(key & 0xffffffffu);
            const float* r = reg + (size_t)(img * NN + idx) * REG_CH;
            float* dst = rowsbuf + rr * RSTRIDE;
            float a = r[lane];
            float b = r[32 + lane];
            float c = 0.0f;
            if (lane < 12)      c = r[64 + lane];
            else if (lane < 15) c = xyz[(size_t)(img * NN + idx) * 3 + (lane - 12)];
            dst[lane]      = a;
            dst[32 + lane] = b;
            if (lane < 15) dst[64 + lane] = c;
            if (lane == 15) scoreS[rr] = key_to_score((unsigned)(key >> 32));
        }
    }
    __syncthreads();

    // ========== Stage B2: decode from smem (thread-per-row, conflict-free) ==========
    const float ah = anchor[0], aw = anchor[1], al = anchor[2];
    if (tid < PSEL) {
        const float* r = rowsbuf + tid * RSTRIDE;

        int xb = 0; float bv = r[0];
        #pragma unroll
        for (int t = 1; t < 12; t++) if (r[t] > bv) { bv = r[t]; xb = t; }
        int zb = 0; bv = r[12];
        #pragma unroll
        for (int t = 1; t < 12; t++) if (r[12 + t] > bv) { bv = r[12 + t]; zb = t; }

        float pos_x = __fadd_rn(__fsub_rn(__fadd_rn(__fmul_rn((float)xb, 0.5f), 0.25f), 3.0f),
                                __fmul_rn(r[24 + xb], 0.5f));
        float pos_z = __fadd_rn(__fsub_rn(__fadd_rn(__fmul_rn((float)zb, 0.5f), 0.25f), 3.0f),
                                __fmul_rn(r[36 + zb], 0.5f));
        float x = __fadd_rn(pos_x, r[76]);
        float z = __fadd_rn(pos_z, r[78]);
        float y = __fadd_rn(r[77], r[48]);

        int rb = 0; bv = r[49];
        #pragma unroll
        for (int t = 1; t < 12; t++) if (r[49 + t] > bv) { bv = r[49 + t]; rb = t; }
        float ry = __fadd_rn(__fmul_rn((float)rb, APC_F),
                             __fmul_rn(r[61 + rb], APC_HALF_F));
        float rem = fmodf(ry, TWO_PI_F);
        if (rem != 0.0f && rem < 0.0f) rem = __fadd_rn(rem, TWO_PI_F);
        ry = rem;
        if (ry > PI_F) ry = __fsub_rn(ry, TWO_PI_F);

        float h = __fadd_rn(__fmul_rn(r[73], ah), ah);
        float w = __fadd_rn(__fmul_rn(r[74], aw), aw);
        float l = __fadd_rn(__fmul_rn(r[75], al), al);
        y = __fadd_rn(y, __fmul_rn(h, 0.5f));

        float* bo = boxS + tid * 7;
        bo[0] = x; bo[1] = y; bo[2] = z; bo[3] = h; bo[4] = w; bo[5] = l; bo[6] = ry;

        float x1 = __fsub_rn(x, __fmul_rn(l, 0.5f));
        float x2 = __fadd_rn(x, __fmul_rn(l, 0.5f));
        float z1 = __fsub_rn(z, __fmul_rn(w, 0.5f));
        float z2 = __fadd_rn(z, __fmul_rn(w, 0.5f));
        sbev[tid] = make_float4(x1, z1, x2, z2);
        sar[tid] = __fmul_rn(__fsub_rn(x2, x1), __fsub_rn(z2, z1));
    }
    __syncthreads();   // rowsbuf dead; sup may now overwrite [0,8192)

    // ========== Stage C: balanced pairwise suppression bitmask + zrow ==========
    {
        const int pr = tid & 127;                // pair id
        const int w = tid >> 7;                  // word 0..7
        #pragma unroll
        for (int half = 0; half < 2; half++) {
            const int i = half ? (PSEL - 1 - pr) : pr;
            float4 bi = sbev[i];
            float ai = sar[i];
            unsigned bits = 0;
            int jbase = w << 5;
            if (jbase + 31 > i) {
                #pragma unroll 4
                for (int b = 0; b < 32; b++) {
                    int j = jbase + b;
                    if (j <= i) continue;
                    float4 bj = sbev[j];
                    float iw = fmaxf(__fsub_rn(fminf(bi.z, bj.z), fmaxf(bi.x, bj.x)), 0.0f);
                    float ih = fmaxf(__fsub_rn(fminf(bi.w, bj.w), fmaxf(bi.y, bj.y)), 0.0f);
                    float inter = __fmul_rn(iw, ih);
                    if (inter > 0.0f) {
                        float denom = __fsub_rn(__fadd_rn(ai, sar[j]), inter);
                        float iou = __fdiv_rn(inter, denom);
                        if (iou > NMS_THRESH) bits |= (1u << b);
                    }
                }
            }
            sup[i * MWS + w] = bits;
            if (bits) atomicOr(&zrow[i >> 5], 1u << (i & 31));
        }
    }
    __syncthreads();

    // ========== Stage D: bulk-skip greedy (warp 0) ==========
    if (wid == 0) {
        unsigned A = (lane < MWS) ? 0xffffffffu : 0u;
        unsigned Z = (lane < MWS) ? zrow[lane] : 0u;
        int cnt = 0;
        int w = 0;
        while (cnt < POST && w < MWS) {
            unsigned word = __shfl_sync(0xffffffffu, A, w);
            unsigned zw   = __shfl_sync(0xffffffffu, Z, w);
            unsigned danger = word & zw;
            if (danger == 0) {
                int nb = __popc(word);
                int take = min(nb, POST - cnt);
                if (lane < take) {
                    int bit = __fns(word, 0, lane + 1);
                    keep[cnt + lane] = (w << 5) + bit;
                }
                cnt += take;
                w++;
            } else {
                int bs = __ffs(danger) - 1;
                unsigned prefix = word & ((1u << bs) - 1u);
                int nb = __popc(prefix);
                int take = min(nb, POST - cnt);
                if (lane < take) {
                    int bit = __fns(prefix, 0, lane + 1);
                    keep[cnt + lane] = (w << 5) + bit;
                }
                cnt += take;
                if (cnt >= POST) break;
                int bi = (w << 5) + bs;
                if (lane == 0) keep[cnt] = bi;
                cnt++;
                unsigned srow = (lane < MWS) ? sup[bi * MWS + lane] : 0u;
                A &= ~srow;
                if (lane == w) {
                    unsigned clr = (bs == 31) ? 0xffffffffu : ((1u << (bs + 1)) - 1u);
                    A &= ~clr;
                }
            }
        }
        if (lane == 0) sKeepCnt = cnt;
    }
    __syncthreads();

    // ========== Stage E: gather output ==========
    const int cnt = sKeepCnt;
    float* ob = out + (size_t)img * POST * 7;
    float* os = out + (size_t)BB * POST * 7 + (size_t)img * POST;
    if (tid < POST) {
        int p = tid;
        if (p < cnt) {
            int ki = keep[p];
            const float* bo = boxS + ki * 7;
            #pragma unroll
            for (int c = 0; c < 7; c++) ob[p * 7 + c] = bo[c];
            os[p] = scoreS[ki];
        } else {
            #pragma unroll
            for (int c = 0; c < 7; c++) ob[p * 7 + c] = 0.0f;
            os[p] = 0.0f;
        }
    }
}

// ============================================================
extern "C" void kernel_launch(void* const* d_in, const int* in_sizes, int n_in,
                              void* d_out, int out_size) {
    const float* scores = (const float*)d_in[0];   // (B,N)
    const float* reg    = (const float*)d_in[1];   // (B,N,76)
    const float* xyz    = (const float*)d_in[2];   // (B,N,3)
    const float* anchor = (const float*)d_in[3];   // (3,)
    float* out = (float*)d_out;

    static bool attr_set = false;
    if (!attr_set) {
        cudaFuncSetAttribute(fused_kernel,
                             cudaFuncAttributeMaxDynamicSharedMemorySize,
                             SMEM_BYTES);
        attr_set = true;
    }

    fused_kernel<<<BB, 1024, SMEM_BYTES>>>(scores, reg, xyz, anchor, out);
}